// round 7
// baseline (speedup 1.0000x reference)
#include <cuda_runtime.h>
#include <math.h>

// ---------------------------------------------------------------------------
// Problem constants
//   B=2, C=512, F=8, H=W=32  -> tokens = 2*8*32*32 = 16384
//   HEADS=8, DIM_HEAD=64, INNER=512, CPB_DIM=256
//   FF_INNER = 1365, 2*FF_INNER = 2730
// ---------------------------------------------------------------------------
#define TOK   16384
#define CDIM  512
#define FFI   1365
#define FF2   2730
#define SCALE 0.125f

// ---------------------------------------------------------------------------
// Scratch (device globals; allocation in kernel_launch is forbidden)
// ---------------------------------------------------------------------------
__device__ float g_xs[TOK * CDIM];       // activations, spatial layout (b,f,hw,c)
__device__ float g_xn[TOK * CDIM];       // rms-normed activations
__device__ float g_q [TOK * CDIM];       // Q
__device__ float g_kv[TOK * 1024];       // [K | V]
__device__ float g_o [TOK * CDIM];       // attention output (pre out-proj)
__device__ float g_t [TOK * CDIM];       // activations, temporal layout (b,hw,f,c)
__device__ float g_yn[TOK * FFI];        // FF normed hidden
__device__ float g_s [134217728ull];     // 536MB: attn scores (16*8*1024*1024) / FF hdn (16384*2730)
__device__ float g_tab2[3969 * 8];       // 2D CPB table
__device__ float g_tab1[15 * 8];         // 1D CPB table

// ---------------------------------------------------------------------------
// Batched 32x32-tile transpose: per batch z, out[j][i] = in[i][j], in is (R, Cc)
// ---------------------------------------------------------------------------
__global__ void transpose_k(const float* __restrict__ in, float* __restrict__ out,
                            int R, int Cc) {
    __shared__ float tile[32][33];
    size_t base = (size_t)blockIdx.z * (size_t)R * (size_t)Cc;
    int c0 = blockIdx.x * 32;
    int r0 = blockIdx.y * 32;
    int tx = threadIdx.x, ty = threadIdx.y;   // 32 x 8
#pragma unroll
    for (int k = 0; k < 32; k += 8)
        tile[ty + k][tx] = in[base + (size_t)(r0 + ty + k) * Cc + c0 + tx];
    __syncthreads();
#pragma unroll
    for (int k = 0; k < 32; k += 8)
        out[base + (size_t)(c0 + ty + k) * R + r0 + tx] = tile[tx][ty + k];
}

// ---------------------------------------------------------------------------
// CPB bias MLPs:  h1 = silu(rel@w1+b1); h2 = silu(h1@w2+b2); out = h2@w3+b3
// ---------------------------------------------------------------------------
__device__ __forceinline__ float silu_f(float v) { return v / (1.0f + expf(-v)); }

__global__ void cpb2_k(const float* __restrict__ w1, const float* __restrict__ b1,
                       const float* __restrict__ w2, const float* __restrict__ b2,
                       const float* __restrict__ w3, const float* __restrict__ b3,
                       float* __restrict__ tab) {
    int r = blockIdx.x;                       // 0..3968
    float gy = (float)(r / 63) - 31.0f;
    float gx = (float)(r % 63) - 31.0f;
    __shared__ float h1[256], h2[256];
    int j = threadIdx.x;                      // 256 threads
    h1[j] = silu_f(gy * w1[j] + gx * w1[256 + j] + b1[j]);
    __syncthreads();
    float acc = b2[j];
    for (int k = 0; k < 256; k++) acc += h1[k] * w2[k * 256 + j];
    h2[j] = silu_f(acc);
    __syncthreads();
    if (j < 8) {
        float a3 = b3[j];
        for (int k = 0; k < 256; k++) a3 += h2[k] * w3[k * 8 + j];
        tab[r * 8 + j] = a3;
    }
}

__global__ void cpb1_k(const float* __restrict__ w1, const float* __restrict__ b1,
                       const float* __restrict__ w2, const float* __restrict__ b2,
                       const float* __restrict__ w3, const float* __restrict__ b3,
                       float* __restrict__ tab) {
    int r = blockIdx.x;                       // 0..14
    float rel = (float)r - 7.0f;
    __shared__ float h1[256], h2[256];
    int j = threadIdx.x;
    h1[j] = silu_f(rel * w1[j] + b1[j]);
    __syncthreads();
    float acc = b2[j];
    for (int k = 0; k < 256; k++) acc += h1[k] * w2[k * 256 + j];
    h2[j] = silu_f(acc);
    __syncthreads();
    if (j < 8) {
        float a3 = b3[j];
        for (int k = 0; k < 256; k++) a3 += h2[k] * w3[k * 8 + j];
        tab[r * 8 + j] = a3;
    }
}

// ---------------------------------------------------------------------------
// RMS norm over last dim (512):  y = x / max(||x||,1e-12) * sqrt(512) * gamma
// ---------------------------------------------------------------------------
__global__ void rmsnorm_k(const float* __restrict__ x, const float* __restrict__ g,
                          float* __restrict__ y) {
    int row = blockIdx.x;
    const float* xr = x + (size_t)row * CDIM;
    int t = threadIdx.x;                      // 256 threads
    float v0 = xr[t], v1 = xr[t + 256];
    __shared__ float red[256];
    red[t] = v0 * v0 + v1 * v1;
    __syncthreads();
    for (int s = 128; s > 0; s >>= 1) {
        if (t < s) red[t] += red[t + s];
        __syncthreads();
    }
    float scale = sqrtf(512.0f) / fmaxf(sqrtf(red[0]), 1e-12f);
    float* yr = y + (size_t)row * CDIM;
    yr[t]       = v0 * scale * g[t];
    yr[t + 256] = v1 * scale * g[t + 256];
}

// ---------------------------------------------------------------------------
// Generic fp32 GEMM: C[M,N] = A[M,K] @ B[K,N] (+ R[M,N] if R != null)
// Tile 128x64x16, 256 threads, 8x4 per thread.
// ---------------------------------------------------------------------------
#define GBM 128
#define GBN 64
#define GBK 16
__global__ void __launch_bounds__(256)
gemm_k(const float* __restrict__ A, const float* __restrict__ B,
       const float* __restrict__ R, float* __restrict__ C,
       int M, int N, int K) {
    __shared__ float As[GBK][GBM + 4];
    __shared__ float Bs[GBK][GBN + 4];
    int block_row = blockIdx.y * GBM;
    int block_col = blockIdx.x * GBN;
    int tid = threadIdx.x;
    int tx = tid & 15;       // col group (4 cols each)
    int ty = tid >> 4;       // row group (8 rows each)
    float acc[8][4];
#pragma unroll
    for (int i = 0; i < 8; i++)
#pragma unroll
        for (int j = 0; j < 4; j++) acc[i][j] = 0.0f;

    for (int k0 = 0; k0 < K; k0 += GBK) {
#pragma unroll
        for (int i = tid; i < GBM * GBK; i += 256) {     // 2048 elems, 8/thread
            int r = i >> 4, kk = i & 15;
            int gr = block_row + r, gk = k0 + kk;
            As[kk][r] = (gr < M && gk < K) ? A[(size_t)gr * K + gk] : 0.0f;
        }
#pragma unroll
        for (int i = tid; i < GBK * GBN; i += 256) {     // 1024 elems, 4/thread
            int kk = i >> 6, c = i & 63;
            int gk = k0 + kk, gc = block_col + c;
            Bs[kk][c] = (gk < K && gc < N) ? B[(size_t)gk * N + gc] : 0.0f;
        }
        __syncthreads();
#pragma unroll
        for (int kk = 0; kk < GBK; kk++) {
            float a[8], b[4];
#pragma unroll
            for (int i = 0; i < 8; i++) a[i] = As[kk][ty * 8 + i];
#pragma unroll
            for (int j = 0; j < 4; j++) b[j] = Bs[kk][tx * 4 + j];
#pragma unroll
            for (int i = 0; i < 8; i++)
#pragma unroll
                for (int j = 0; j < 4; j++) acc[i][j] += a[i] * b[j];
        }
        __syncthreads();
    }
#pragma unroll
    for (int i = 0; i < 8; i++) {
        int gr = block_row + ty * 8 + i;
        if (gr >= M) continue;
#pragma unroll
        for (int j = 0; j < 4; j++) {
            int gc = block_col + tx * 4 + j;
            if (gc >= N) continue;
            float v = acc[i][j];
            if (R) v += R[(size_t)gr * N + gc];
            C[(size_t)gr * N + gc] = v;
        }
    }
}

// ---------------------------------------------------------------------------
// Spatial attention scores: s[bh,i,j] = (q_i . k_j)*SCALE + cpb2_bias(i,j,h)
// grid (16 jtile, 16 itile, 128 bh), 256 thr, 64x64 tile, K=64
// ---------------------------------------------------------------------------
__global__ void __launch_bounds__(256)
scores_k(const float* __restrict__ q, const float* __restrict__ kv,
         const float* __restrict__ tab, float* __restrict__ s) {
    int bh = blockIdx.z;
    int b = bh >> 3, h = bh & 7;
    int i0 = blockIdx.y * 64, j0 = blockIdx.x * 64;
    const float* qb = q  + (size_t)b * 1024 * 512  + h * 64;
    const float* kb = kv + (size_t)b * 1024 * 1024 + h * 64;
    __shared__ float As[16][68], Bs[16][68];
    int tid = threadIdx.x;
    int tx = tid & 15, ty = tid >> 4;
    float acc[4][4];
#pragma unroll
    for (int i = 0; i < 4; i++)
#pragma unroll
        for (int j = 0; j < 4; j++) acc[i][j] = 0.0f;

    int lr  = tid >> 2;            // 0..63
    int lk4 = (tid & 3) * 4;       // 0,4,8,12
    for (int k0 = 0; k0 < 64; k0 += 16) {
        float4 a4 = *reinterpret_cast<const float4*>(qb + (size_t)(i0 + lr) * 512 + k0 + lk4);
        As[lk4 + 0][lr] = a4.x; As[lk4 + 1][lr] = a4.y;
        As[lk4 + 2][lr] = a4.z; As[lk4 + 3][lr] = a4.w;
        float4 b4 = *reinterpret_cast<const float4*>(kb + (size_t)(j0 + lr) * 1024 + k0 + lk4);
        Bs[lk4 + 0][lr] = b4.x; Bs[lk4 + 1][lr] = b4.y;
        Bs[lk4 + 2][lr] = b4.z; Bs[lk4 + 3][lr] = b4.w;
        __syncthreads();
#pragma unroll
        for (int kk = 0; kk < 16; kk++) {
            float a[4], b[4];
#pragma unroll
            for (int i = 0; i < 4; i++) a[i] = As[kk][ty * 4 + i];
#pragma unroll
            for (int j = 0; j < 4; j++) b[j] = Bs[kk][tx * 4 + j];
#pragma unroll
            for (int i = 0; i < 4; i++)
#pragma unroll
                for (int j = 0; j < 4; j++) acc[i][j] += a[i] * b[j];
        }
        __syncthreads();
    }
#pragma unroll
    for (int i = 0; i < 4; i++) {
        int gi = i0 + ty * 4 + i;
#pragma unroll
        for (int j = 0; j < 4; j++) {
            int gj = j0 + tx * 4 + j;
            int dy = (gi >> 5) - (gj >> 5) + 31;
            int dx = (gi & 31) - (gj & 31) + 31;
            float bias = tab[(dy * 63 + dx) * 8 + h];
            s[((size_t)bh * 1024 + gi) * 1024 + gj] = acc[i][j] * SCALE + bias;
        }
    }
}

// ---------------------------------------------------------------------------
// Row softmax over 1024 (scores already include bias), in place
// ---------------------------------------------------------------------------
__global__ void softmax_k(float* __restrict__ s) {
    size_t row = blockIdx.x;
    float* p = s + row * 1024;
    int t = threadIdx.x;                       // 256
    float v[4];
    float m = -3.4e38f;
#pragma unroll
    for (int i = 0; i < 4; i++) { v[i] = p[t + i * 256]; m = fmaxf(m, v[i]); }
    __shared__ float red[256];
    red[t] = m; __syncthreads();
    for (int st = 128; st > 0; st >>= 1) {
        if (t < st) red[t] = fmaxf(red[t], red[t + st]);
        __syncthreads();
    }
    m = red[0];
    __syncthreads();
    float sum = 0.0f;
#pragma unroll
    for (int i = 0; i < 4; i++) { v[i] = expf(v[i] - m); sum += v[i]; }
    red[t] = sum; __syncthreads();
    for (int st = 128; st > 0; st >>= 1) {
        if (t < st) red[t] += red[t + st];
        __syncthreads();
    }
    float inv = 1.0f / red[0];
#pragma unroll
    for (int i = 0; i < 4; i++) p[t + i * 256] = v[i] * inv;
}

// ---------------------------------------------------------------------------
// AV: o[bh, i, :] = a[bh, i, :] @ V[bh]   (1024x64 = 1024x1024 @ 1024x64)
// grid (1, 16 itile, 128 bh)
// ---------------------------------------------------------------------------
__global__ void __launch_bounds__(256)
av_k(const float* __restrict__ s, const float* __restrict__ kv,
     float* __restrict__ o) {
    int bh = blockIdx.z;
    int b = bh >> 3, h = bh & 7;
    int i0 = blockIdx.y * 64;
    const float* sb = s  + (size_t)bh * 1024 * 1024;
    const float* vb = kv + (size_t)b * 1024 * 1024 + 512 + h * 64;
    __shared__ float As[16][68], Bs[16][68];
    int tid = threadIdx.x;
    int tx = tid & 15, ty = tid >> 4;
    float acc[4][4];
#pragma unroll
    for (int i = 0; i < 4; i++)
#pragma unroll
        for (int j = 0; j < 4; j++) acc[i][j] = 0.0f;

    int ar  = tid >> 2;           // 0..63
    int ak4 = (tid & 3) * 4;
    int bk  = tid >> 4;           // 0..15
    int bc4 = (tid & 15) * 4;
    for (int k0 = 0; k0 < 1024; k0 += 16) {
        float4 a4 = *reinterpret_cast<const float4*>(sb + (size_t)(i0 + ar) * 1024 + k0 + ak4);
        As[ak4 + 0][ar] = a4.x; As[ak4 + 1][ar] = a4.y;
        As[ak4 + 2][ar] = a4.z; As[ak4 + 3][ar] = a4.w;
        float4 b4 = *reinterpret_cast<const float4*>(vb + (size_t)(k0 + bk) * 1024 + bc4);
        Bs[bk][bc4 + 0] = b4.x; Bs[bk][bc4 + 1] = b4.y;
        Bs[bk][bc4 + 2] = b4.z; Bs[bk][bc4 + 3] = b4.w;
        __syncthreads();
#pragma unroll
        for (int kk = 0; kk < 16; kk++) {
            float a[4], b[4];
#pragma unroll
            for (int i = 0; i < 4; i++) a[i] = As[kk][ty * 4 + i];
#pragma unroll
            for (int j = 0; j < 4; j++) b[j] = Bs[kk][tx * 4 + j];
#pragma unroll
            for (int i = 0; i < 4; i++)
#pragma unroll
                for (int j = 0; j < 4; j++) acc[i][j] += a[i] * b[j];
        }
        __syncthreads();
    }
#pragma unroll
    for (int i = 0; i < 4; i++) {
        int gi = i0 + ty * 4 + i;
#pragma unroll
        for (int j = 0; j < 4; j++)
            o[((size_t)b * 1024 + gi) * 512 + h * 64 + tx * 4 + j] = acc[i][j];
    }
}

// ---------------------------------------------------------------------------
// Temporal attention, fully fused: one warp per (b2, head), n=8, d=64
// ---------------------------------------------------------------------------
__global__ void __launch_bounds__(256)
tattn_k(const float* __restrict__ q, const float* __restrict__ kv,
        const float* __restrict__ tab, float* __restrict__ o) {
    int b2 = blockIdx.x;                      // 0..2047
    int h = threadIdx.x >> 5;                 // 8 warps = 8 heads
    int lane = threadIdx.x & 31;
    const float* qb = q  + (size_t)b2 * 4096 + h * 64;
    const float* kb = kv + (size_t)b2 * 8192 + h * 64;
    const float* vb = kb + 512;
    float kr[8], kr2[8], vr[8], vr2[8];
#pragma unroll
    for (int j = 0; j < 8; j++) {
        kr[j]  = kb[j * 1024 + lane];      kr2[j] = kb[j * 1024 + lane + 32];
        vr[j]  = vb[j * 1024 + lane];      vr2[j] = vb[j * 1024 + lane + 32];
    }
#pragma unroll 1
    for (int i = 0; i < 8; i++) {
        float qv  = qb[i * 512 + lane];
        float qv2 = qb[i * 512 + lane + 32];
        float sc[8];
#pragma unroll
        for (int j = 0; j < 8; j++) {
            float p = qv * kr[j] + qv2 * kr2[j];
#pragma unroll
            for (int off = 16; off > 0; off >>= 1)
                p += __shfl_xor_sync(0xffffffffu, p, off);
            sc[j] = p * SCALE + tab[(i - j + 7) * 8 + h];
        }
        float m = sc[0];
#pragma unroll
        for (int j = 1; j < 8; j++) m = fmaxf(m, sc[j]);
        float sum = 0.0f;
#pragma unroll
        for (int j = 0; j < 8; j++) { sc[j] = expf(sc[j] - m); sum += sc[j]; }
        float inv = 1.0f / sum;
        float o1 = 0.0f, o2 = 0.0f;
#pragma unroll
        for (int j = 0; j < 8; j++) { o1 += sc[j] * vr[j]; o2 += sc[j] * vr2[j]; }
        float* ob = o + (size_t)(b2 * 8 + i) * 512 + h * 64;
        ob[lane]      = o1 * inv;
        ob[lane + 32] = o2 * inv;
    }
}

// ---------------------------------------------------------------------------
// Layout swaps: spatial rows (b*8+f)*1024+hw  <->  temporal rows (b*1024+hw)*8+f
// ---------------------------------------------------------------------------
__global__ void sp2tmp_k(const float* __restrict__ in, float* __restrict__ out) {
    size_t idx = (size_t)blockIdx.x * 256 + threadIdx.x;
    int c  = (int)(idx & 511);
    int rt = (int)(idx >> 9);
    int f  = rt & 7;
    int bw = rt >> 3;                 // b*1024 + hw
    int b  = bw >> 10;
    int hw = bw & 1023;
    int rs = ((b << 3) + f) * 1024 + hw;
    out[idx] = in[(size_t)rs * 512 + c];
}
__global__ void tmp2sp_k(const float* __restrict__ in, float* __restrict__ out) {
    size_t idx = (size_t)blockIdx.x * 256 + threadIdx.x;
    int c  = (int)(idx & 511);
    int rs = (int)(idx >> 9);
    int hw = rs & 1023;
    int bf = rs >> 10;
    int b  = bf >> 3;
    int f  = bf & 7;
    int rt = ((b << 10) + hw) * 8 + f;
    out[idx] = in[(size_t)rt * 512 + c];
}

// ---------------------------------------------------------------------------
// FF activation: y = a * gelu(gate) with f-axis channel shift for c>=683,
// then rms-norm(1365) * ff_gamma
// ---------------------------------------------------------------------------
__global__ void ff_act_rms_k(const float* __restrict__ hdn,
                             const float* __restrict__ gamma,
                             float* __restrict__ yn) {
    int r = blockIdx.x;                       // spatial row (b*8+f)*1024+hw
    int f = (r >> 10) & 7;
    const float* row0 = hdn + (size_t)r * FF2;
    const float* row1 = (f > 0) ? (hdn + (size_t)(r - 1024) * FF2) : (const float*)0;
    __shared__ float ybuf[FFI];
    __shared__ float red[256];
    int t = threadIdx.x;
    float ss = 0.0f;
    for (int c = t; c < FFI; c += 256) {
        float a, g;
        if (c < 683)      { a = row0[c]; g = row0[FFI + c]; }
        else if (row1)    { a = row1[c]; g = row1[FFI + c]; }
        else              { a = 0.0f;    g = 0.0f; }
        float gl = 0.5f * g * (1.0f + erff(g * 0.70710678118654752f));
        float y = a * gl;
        ybuf[c] = y;
        ss += y * y;
    }
    red[t] = ss; __syncthreads();
    for (int st = 128; st > 0; st >>= 1) {
        if (t < st) red[t] += red[t + st];
        __syncthreads();
    }
    float scale = sqrtf((float)FFI) / fmaxf(sqrtf(red[0]), 1e-12f);
    for (int c = t; c < FFI; c += 256)
        yn[(size_t)r * FFI + c] = ybuf[c] * scale * gamma[c];
}

// ---------------------------------------------------------------------------
// Host orchestration
// ---------------------------------------------------------------------------
static float *p_xs = 0, *p_xn, *p_q, *p_kv, *p_o, *p_t, *p_yn, *p_s, *p_tab2, *p_tab1;

static void init_ptrs() {
    if (p_xs) return;
    cudaGetSymbolAddress((void**)&p_xs,   g_xs);
    cudaGetSymbolAddress((void**)&p_xn,   g_xn);
    cudaGetSymbolAddress((void**)&p_q,    g_q);
    cudaGetSymbolAddress((void**)&p_kv,   g_kv);
    cudaGetSymbolAddress((void**)&p_o,    g_o);
    cudaGetSymbolAddress((void**)&p_t,    g_t);
    cudaGetSymbolAddress((void**)&p_yn,   g_yn);
    cudaGetSymbolAddress((void**)&p_s,    g_s);
    cudaGetSymbolAddress((void**)&p_tab2, g_tab2);
    cudaGetSymbolAddress((void**)&p_tab1, g_tab1);
}

extern "C" void kernel_launch(void* const* d_in, const int* in_sizes, int n_in,
                              void* d_out, int out_size) {
    (void)in_sizes; (void)n_in; (void)out_size;
    init_ptrs();

    const float* x        = (const float*)d_in[0];
    const float* sa_gamma = (const float*)d_in[1];
    const float* sa_wq    = (const float*)d_in[2];
    const float* sa_wkv   = (const float*)d_in[3];
    const float* sa_wo    = (const float*)d_in[4];
    const float* ta_gamma = (const float*)d_in[5];
    const float* ta_wq    = (const float*)d_in[6];
    const float* ta_wkv   = (const float*)d_in[7];
    const float* ta_wo    = (const float*)d_in[8];
    const float* sp_w1    = (const float*)d_in[9];
    const float* sp_b1    = (const float*)d_in[10];
    const float* sp_w2    = (const float*)d_in[11];
    const float* sp_b2    = (const float*)d_in[12];
    const float* sp_w3    = (const float*)d_in[13];
    const float* sp_b3    = (const float*)d_in[14];
    const float* tp_w1    = (const float*)d_in[15];
    const float* tp_b1    = (const float*)d_in[16];
    const float* tp_w2    = (const float*)d_in[17];
    const float* tp_b2    = (const float*)d_in[18];
    const float* tp_w3    = (const float*)d_in[19];
    const float* tp_b3    = (const float*)d_in[20];
    const float* ff_win   = (const float*)d_in[21];
    const float* ff_gamma = (const float*)d_in[22];
    const float* ff_wout  = (const float*)d_in[23];
    float* out = (float*)d_out;

    dim3 tb(32, 8);

    // (B,C,F,H,W) -> spatial layout (b,f,hw,c): per b transpose (512 x 8192)
    transpose_k<<<dim3(8192 / 32, 512 / 32, 2), tb>>>(x, p_xs, 512, 8192);

    // CPB bias tables
    cpb2_k<<<3969, 256>>>(sp_w1, sp_b1, sp_w2, sp_b2, sp_w3, sp_b3, p_tab2);
    cpb1_k<<<15,   256>>>(tp_w1, tp_b1, tp_w2, tp_b2, tp_w3, tp_b3, p_tab1);

    // ---- spatial attention ----
    rmsnorm_k<<<TOK, 256>>>(p_xs, sa_gamma, p_xn);
    gemm_k<<<dim3(512 / GBN,  TOK / GBM), 256>>>(p_xn, sa_wq,  0, p_q,  TOK, 512,  512);
    gemm_k<<<dim3(1024 / GBN, TOK / GBM), 256>>>(p_xn, sa_wkv, 0, p_kv, TOK, 1024, 512);
    scores_k<<<dim3(16, 16, 128), 256>>>(p_q, p_kv, p_tab2, p_s);
    softmax_k<<<131072, 256>>>(p_s);
    av_k<<<dim3(1, 16, 128), 256>>>(p_s, p_kv, p_o);
    gemm_k<<<dim3(512 / GBN, TOK / GBM), 256>>>(p_o, sa_wo, p_xs, p_xs, TOK, 512, 512);

    // ---- temporal attention ----
    sp2tmp_k<<<TOK * 512 / 256, 256>>>(p_xs, p_t);
    rmsnorm_k<<<TOK, 256>>>(p_t, ta_gamma, p_xn);
    gemm_k<<<dim3(512 / GBN,  TOK / GBM), 256>>>(p_xn, ta_wq,  0, p_q,  TOK, 512,  512);
    gemm_k<<<dim3(1024 / GBN, TOK / GBM), 256>>>(p_xn, ta_wkv, 0, p_kv, TOK, 1024, 512);
    tattn_k<<<2048, 256>>>(p_q, p_kv, p_tab1, p_o);
    gemm_k<<<dim3(512 / GBN, TOK / GBM), 256>>>(p_o, ta_wo, p_t, p_t, TOK, 512, 512);
    tmp2sp_k<<<TOK * 512 / 256, 256>>>(p_t, p_xs);

    // ---- feed-forward ----
    gemm_k<<<dim3((FF2 + GBN - 1) / GBN, TOK / GBM), 256>>>(p_xs, ff_win, 0, p_s, TOK, FF2, 512);
    ff_act_rms_k<<<TOK, 256>>>(p_s, ff_gamma, p_yn);
    gemm_k<<<dim3(512 / GBN, TOK / GBM), 256>>>(p_yn, ff_wout, p_xs, p_xs, TOK, 512, FFI);

    // spatial layout -> (B,C,F,H,W): per b transpose (8192 x 512)
    transpose_k<<<dim3(512 / 32, 8192 / 32, 2), tb>>>(p_xs, out, 8192, 512);
}

// round 8
// speedup vs baseline: 1.0006x; 1.0006x over previous
#include <cuda_runtime.h>
#include <math.h>

// ---------------------------------------------------------------------------
// Problem constants
//   B=2, C=512, F=8, H=W=32  -> tokens = 2*8*32*32 = 16384
//   HEADS=8, DIM_HEAD=64, INNER=512, CPB_DIM=256
//   FF_INNER = 1365, 2*FF_INNER = 2730
// ---------------------------------------------------------------------------
#define TOK   16384
#define CDIM  512
#define FFI   1365
#define FF2   2730
#define SCALE 0.125f

// ---------------------------------------------------------------------------
// Scratch (device globals; allocation in kernel_launch is forbidden)
// ---------------------------------------------------------------------------
__device__ float g_xs[TOK * CDIM];       // activations, spatial layout (b,f,hw,c)
__device__ float g_xn[TOK * CDIM];       // rms-normed activations
__device__ float g_q [TOK * CDIM];       // Q
__device__ float g_kv[TOK * 1024];       // [K | V]
__device__ float g_o [TOK * CDIM];       // attention output (pre out-proj)
__device__ float g_t [TOK * CDIM];       // activations, temporal layout (b,hw,f,c)
__device__ float g_yn[TOK * FFI];        // FF normed hidden
__device__ float g_s [134217728ull];     // 536MB: attn scores (16*8*1024*1024) / FF hdn (16384*2730)
__device__ float g_tab2[3969 * 8];       // 2D CPB table
__device__ float g_tab1[15 * 8];         // 1D CPB table

// ---------------------------------------------------------------------------
// Batched 32x32-tile transpose: per batch z, out[j][i] = in[i][j], in is (R, Cc)
// ---------------------------------------------------------------------------
__global__ void transpose_k(const float* __restrict__ in, float* __restrict__ out,
                            int R, int Cc) {
    __shared__ float tile[32][33];
    size_t base = (size_t)blockIdx.z * (size_t)R * (size_t)Cc;
    int c0 = blockIdx.x * 32;
    int r0 = blockIdx.y * 32;
    int tx = threadIdx.x, ty = threadIdx.y;   // 32 x 8
#pragma unroll
    for (int k = 0; k < 32; k += 8)
        tile[ty + k][tx] = in[base + (size_t)(r0 + ty + k) * Cc + c0 + tx];
    __syncthreads();
#pragma unroll
    for (int k = 0; k < 32; k += 8)
        out[base + (size_t)(c0 + ty + k) * R + r0 + tx] = tile[tx][ty + k];
}

// ---------------------------------------------------------------------------
// CPB bias MLPs:  h1 = silu(rel@w1+b1); h2 = silu(h1@w2+b2); out = h2@w3+b3
// ---------------------------------------------------------------------------
__device__ __forceinline__ float silu_f(float v) { return v / (1.0f + expf(-v)); }

__global__ void cpb2_k(const float* __restrict__ w1, const float* __restrict__ b1,
                       const float* __restrict__ w2, const float* __restrict__ b2,
                       const float* __restrict__ w3, const float* __restrict__ b3,
                       float* __restrict__ tab) {
    int r = blockIdx.x;                       // 0..3968
    float gy = (float)(r / 63) - 31.0f;
    float gx = (float)(r % 63) - 31.0f;
    __shared__ float h1[256], h2[256];
    int j = threadIdx.x;                      // 256 threads
    h1[j] = silu_f(gy * w1[j] + gx * w1[256 + j] + b1[j]);
    __syncthreads();
    float acc = b2[j];
    for (int k = 0; k < 256; k++) acc += h1[k] * w2[k * 256 + j];
    h2[j] = silu_f(acc);
    __syncthreads();
    if (j < 8) {
        float a3 = b3[j];
        for (int k = 0; k < 256; k++) a3 += h2[k] * w3[k * 8 + j];
        tab[r * 8 + j] = a3;
    }
}

__global__ void cpb1_k(const float* __restrict__ w1, const float* __restrict__ b1,
                       const float* __restrict__ w2, const float* __restrict__ b2,
                       const float* __restrict__ w3, const float* __restrict__ b3,
                       float* __restrict__ tab) {
    int r = blockIdx.x;                       // 0..14
    float rel = (float)r - 7.0f;
    __shared__ float h1[256], h2[256];
    int j = threadIdx.x;
    h1[j] = silu_f(rel * w1[j] + b1[j]);
    __syncthreads();
    float acc = b2[j];
    for (int k = 0; k < 256; k++) acc += h1[k] * w2[k * 256 + j];
    h2[j] = silu_f(acc);
    __syncthreads();
    if (j < 8) {
        float a3 = b3[j];
        for (int k = 0; k < 256; k++) a3 += h2[k] * w3[k * 8 + j];
        tab[r * 8 + j] = a3;
    }
}

// ---------------------------------------------------------------------------
// RMS norm over last dim (512):  y = x / max(||x||,1e-12) * sqrt(512) * gamma
// ---------------------------------------------------------------------------
__global__ void rmsnorm_k(const float* __restrict__ x, const float* __restrict__ g,
                          float* __restrict__ y) {
    int row = blockIdx.x;
    const float* xr = x + (size_t)row * CDIM;
    int t = threadIdx.x;                      // 256 threads
    float v0 = xr[t], v1 = xr[t + 256];
    __shared__ float red[256];
    red[t] = v0 * v0 + v1 * v1;
    __syncthreads();
    for (int s = 128; s > 0; s >>= 1) {
        if (t < s) red[t] += red[t + s];
        __syncthreads();
    }
    float scale = sqrtf(512.0f) / fmaxf(sqrtf(red[0]), 1e-12f);
    float* yr = y + (size_t)row * CDIM;
    yr[t]       = v0 * scale * g[t];
    yr[t + 256] = v1 * scale * g[t + 256];
}

// ---------------------------------------------------------------------------
// Generic fp32 GEMM: C[M,N] = A[M,K] @ B[K,N] (+ R[M,N] if R != null)
// Tile 128x64x16, 256 threads, 8x4 per thread.
// ---------------------------------------------------------------------------
#define GBM 128
#define GBN 64
#define GBK 16
__global__ void __launch_bounds__(256)
gemm_k(const float* __restrict__ A, const float* __restrict__ B,
       const float* __restrict__ R, float* __restrict__ C,
       int M, int N, int K) {
    __shared__ float As[GBK][GBM + 4];
    __shared__ float Bs[GBK][GBN + 4];
    int block_row = blockIdx.y * GBM;
    int block_col = blockIdx.x * GBN;
    int tid = threadIdx.x;
    int tx = tid & 15;       // col group (4 cols each)
    int ty = tid >> 4;       // row group (8 rows each)
    float acc[8][4];
#pragma unroll
    for (int i = 0; i < 8; i++)
#pragma unroll
        for (int j = 0; j < 4; j++) acc[i][j] = 0.0f;

    for (int k0 = 0; k0 < K; k0 += GBK) {
#pragma unroll
        for (int i = tid; i < GBM * GBK; i += 256) {     // 2048 elems, 8/thread
            int r = i >> 4, kk = i & 15;
            int gr = block_row + r, gk = k0 + kk;
            As[kk][r] = (gr < M && gk < K) ? A[(size_t)gr * K + gk] : 0.0f;
        }
#pragma unroll
        for (int i = tid; i < GBK * GBN; i += 256) {     // 1024 elems, 4/thread
            int kk = i >> 6, c = i & 63;
            int gk = k0 + kk, gc = block_col + c;
            Bs[kk][c] = (gk < K && gc < N) ? B[(size_t)gk * N + gc] : 0.0f;
        }
        __syncthreads();
#pragma unroll
        for (int kk = 0; kk < GBK; kk++) {
            float a[8], b[4];
#pragma unroll
            for (int i = 0; i < 8; i++) a[i] = As[kk][ty * 8 + i];
#pragma unroll
            for (int j = 0; j < 4; j++) b[j] = Bs[kk][tx * 4 + j];
#pragma unroll
            for (int i = 0; i < 8; i++)
#pragma unroll
                for (int j = 0; j < 4; j++) acc[i][j] += a[i] * b[j];
        }
        __syncthreads();
    }
#pragma unroll
    for (int i = 0; i < 8; i++) {
        int gr = block_row + ty * 8 + i;
        if (gr >= M) continue;
#pragma unroll
        for (int j = 0; j < 4; j++) {
            int gc = block_col + tx * 4 + j;
            if (gc >= N) continue;
            float v = acc[i][j];
            if (R) v += R[(size_t)gr * N + gc];
            C[(size_t)gr * N + gc] = v;
        }
    }
}

// ---------------------------------------------------------------------------
// Spatial attention scores: s[bh,i,j] = (q_i . k_j)*SCALE + cpb2_bias(i,j,h)
// grid (16 jtile, 16 itile, 128 bh), 256 thr, 64x64 tile, K=64
// ---------------------------------------------------------------------------
__global__ void __launch_bounds__(256)
scores_k(const float* __restrict__ q, const float* __restrict__ kv,
         const float* __restrict__ tab, float* __restrict__ s) {
    int bh = blockIdx.z;
    int b = bh >> 3, h = bh & 7;
    int i0 = blockIdx.y * 64, j0 = blockIdx.x * 64;
    const float* qb = q  + (size_t)b * 1024 * 512  + h * 64;
    const float* kb = kv + (size_t)b * 1024 * 1024 + h * 64;
    __shared__ float As[16][68], Bs[16][68];
    int tid = threadIdx.x;
    int tx = tid & 15, ty = tid >> 4;
    float acc[4][4];
#pragma unroll
    for (int i = 0; i < 4; i++)
#pragma unroll
        for (int j = 0; j < 4; j++) acc[i][j] = 0.0f;

    int lr  = tid >> 2;            // 0..63
    int lk4 = (tid & 3) * 4;       // 0,4,8,12
    for (int k0 = 0; k0 < 64; k0 += 16) {
        float4 a4 = *reinterpret_cast<const float4*>(qb + (size_t)(i0 + lr) * 512 + k0 + lk4);
        As[lk4 + 0][lr] = a4.x; As[lk4 + 1][lr] = a4.y;
        As[lk4 + 2][lr] = a4.z; As[lk4 + 3][lr] = a4.w;
        float4 b4 = *reinterpret_cast<const float4*>(kb + (size_t)(j0 + lr) * 1024 + k0 + lk4);
        Bs[lk4 + 0][lr] = b4.x; Bs[lk4 + 1][lr] = b4.y;
        Bs[lk4 + 2][lr] = b4.z; Bs[lk4 + 3][lr] = b4.w;
        __syncthreads();
#pragma unroll
        for (int kk = 0; kk < 16; kk++) {
            float a[4], b[4];
#pragma unroll
            for (int i = 0; i < 4; i++) a[i] = As[kk][ty * 4 + i];
#pragma unroll
            for (int j = 0; j < 4; j++) b[j] = Bs[kk][tx * 4 + j];
#pragma unroll
            for (int i = 0; i < 4; i++)
#pragma unroll
                for (int j = 0; j < 4; j++) acc[i][j] += a[i] * b[j];
        }
        __syncthreads();
    }
#pragma unroll
    for (int i = 0; i < 4; i++) {
        int gi = i0 + ty * 4 + i;
#pragma unroll
        for (int j = 0; j < 4; j++) {
            int gj = j0 + tx * 4 + j;
            int dy = (gi >> 5) - (gj >> 5) + 31;
            int dx = (gi & 31) - (gj & 31) + 31;
            float bias = tab[(dy * 63 + dx) * 8 + h];
            s[((size_t)bh * 1024 + gi) * 1024 + gj] = acc[i][j] * SCALE + bias;
        }
    }
}

// ---------------------------------------------------------------------------
// Row softmax over 1024 (scores already include bias), in place
// ---------------------------------------------------------------------------
__global__ void softmax_k(float* __restrict__ s) {
    size_t row = blockIdx.x;
    float* p = s + row * 1024;
    int t = threadIdx.x;                       // 256
    float v[4];
    float m = -3.4e38f;
#pragma unroll
    for (int i = 0; i < 4; i++) { v[i] = p[t + i * 256]; m = fmaxf(m, v[i]); }
    __shared__ float red[256];
    red[t] = m; __syncthreads();
    for (int st = 128; st > 0; st >>= 1) {
        if (t < st) red[t] = fmaxf(red[t], red[t + st]);
        __syncthreads();
    }
    m = red[0];
    __syncthreads();
    float sum = 0.0f;
#pragma unroll
    for (int i = 0; i < 4; i++) { v[i] = expf(v[i] - m); sum += v[i]; }
    red[t] = sum; __syncthreads();
    for (int st = 128; st > 0; st >>= 1) {
        if (t < st) red[t] += red[t + st];
        __syncthreads();
    }
    float inv = 1.0f / red[0];
#pragma unroll
    for (int i = 0; i < 4; i++) p[t + i * 256] = v[i] * inv;
}

// ---------------------------------------------------------------------------
// AV: o[bh, i, :] = a[bh, i, :] @ V[bh]   (1024x64 = 1024x1024 @ 1024x64)
// grid (1, 16 itile, 128 bh)
// ---------------------------------------------------------------------------
__global__ void __launch_bounds__(256)
av_k(const float* __restrict__ s, const float* __restrict__ kv,
     float* __restrict__ o) {
    int bh = blockIdx.z;
    int b = bh >> 3, h = bh & 7;
    int i0 = blockIdx.y * 64;
    const float* sb = s  + (size_t)bh * 1024 * 1024;
    const float* vb = kv + (size_t)b * 1024 * 1024 + 512 + h * 64;
    __shared__ float As[16][68], Bs[16][68];
    int tid = threadIdx.x;
    int tx = tid & 15, ty = tid >> 4;
    float acc[4][4];
#pragma unroll
    for (int i = 0; i < 4; i++)
#pragma unroll
        for (int j = 0; j < 4; j++) acc[i][j] = 0.0f;

    int ar  = tid >> 2;           // 0..63
    int ak4 = (tid & 3) * 4;
    int bk  = tid >> 4;           // 0..15
    int bc4 = (tid & 15) * 4;
    for (int k0 = 0; k0 < 1024; k0 += 16) {
        float4 a4 = *reinterpret_cast<const float4*>(sb + (size_t)(i0 + ar) * 1024 + k0 + ak4);
        As[ak4 + 0][ar] = a4.x; As[ak4 + 1][ar] = a4.y;
        As[ak4 + 2][ar] = a4.z; As[ak4 + 3][ar] = a4.w;
        float4 b4 = *reinterpret_cast<const float4*>(vb + (size_t)(k0 + bk) * 1024 + bc4);
        Bs[bk][bc4 + 0] = b4.x; Bs[bk][bc4 + 1] = b4.y;
        Bs[bk][bc4 + 2] = b4.z; Bs[bk][bc4 + 3] = b4.w;
        __syncthreads();
#pragma unroll
        for (int kk = 0; kk < 16; kk++) {
            float a[4], b[4];
#pragma unroll
            for (int i = 0; i < 4; i++) a[i] = As[kk][ty * 4 + i];
#pragma unroll
            for (int j = 0; j < 4; j++) b[j] = Bs[kk][tx * 4 + j];
#pragma unroll
            for (int i = 0; i < 4; i++)
#pragma unroll
                for (int j = 0; j < 4; j++) acc[i][j] += a[i] * b[j];
        }
        __syncthreads();
    }
#pragma unroll
    for (int i = 0; i < 4; i++) {
        int gi = i0 + ty * 4 + i;
#pragma unroll
        for (int j = 0; j < 4; j++)
            o[((size_t)b * 1024 + gi) * 512 + h * 64 + tx * 4 + j] = acc[i][j];
    }
}

// ---------------------------------------------------------------------------
// Temporal attention, fully fused: one warp per (b2, head), n=8, d=64
// ---------------------------------------------------------------------------
__global__ void __launch_bounds__(256)
tattn_k(const float* __restrict__ q, const float* __restrict__ kv,
        const float* __restrict__ tab, float* __restrict__ o) {
    int b2 = blockIdx.x;                      // 0..2047
    int h = threadIdx.x >> 5;                 // 8 warps = 8 heads
    int lane = threadIdx.x & 31;
    const float* qb = q  + (size_t)b2 * 4096 + h * 64;
    const float* kb = kv + (size_t)b2 * 8192 + h * 64;
    const float* vb = kb + 512;
    float kr[8], kr2[8], vr[8], vr2[8];
#pragma unroll
    for (int j = 0; j < 8; j++) {
        kr[j]  = kb[j * 1024 + lane];      kr2[j] = kb[j * 1024 + lane + 32];
        vr[j]  = vb[j * 1024 + lane];      vr2[j] = vb[j * 1024 + lane + 32];
    }
#pragma unroll 1
    for (int i = 0; i < 8; i++) {
        float qv  = qb[i * 512 + lane];
        float qv2 = qb[i * 512 + lane + 32];
        float sc[8];
#pragma unroll
        for (int j = 0; j < 8; j++) {
            float p = qv * kr[j] + qv2 * kr2[j];
#pragma unroll
            for (int off = 16; off > 0; off >>= 1)
                p += __shfl_xor_sync(0xffffffffu, p, off);
            sc[j] = p * SCALE + tab[(i - j + 7) * 8 + h];
        }
        float m = sc[0];
#pragma unroll
        for (int j = 1; j < 8; j++) m = fmaxf(m, sc[j]);
        float sum = 0.0f;
#pragma unroll
        for (int j = 0; j < 8; j++) { sc[j] = expf(sc[j] - m); sum += sc[j]; }
        float inv = 1.0f / sum;
        float o1 = 0.0f, o2 = 0.0f;
#pragma unroll
        for (int j = 0; j < 8; j++) { o1 += sc[j] * vr[j]; o2 += sc[j] * vr2[j]; }
        float* ob = o + (size_t)(b2 * 8 + i) * 512 + h * 64;
        ob[lane]      = o1 * inv;
        ob[lane + 32] = o2 * inv;
    }
}

// ---------------------------------------------------------------------------
// Layout swaps: spatial rows (b*8+f)*1024+hw  <->  temporal rows (b*1024+hw)*8+f
// ---------------------------------------------------------------------------
__global__ void sp2tmp_k(const float* __restrict__ in, float* __restrict__ out) {
    size_t idx = (size_t)blockIdx.x * 256 + threadIdx.x;
    int c  = (int)(idx & 511);
    int rt = (int)(idx >> 9);
    int f  = rt & 7;
    int bw = rt >> 3;                 // b*1024 + hw
    int b  = bw >> 10;
    int hw = bw & 1023;
    int rs = ((b << 3) + f) * 1024 + hw;
    out[idx] = in[(size_t)rs * 512 + c];
}
__global__ void tmp2sp_k(const float* __restrict__ in, float* __restrict__ out) {
    size_t idx = (size_t)blockIdx.x * 256 + threadIdx.x;
    int c  = (int)(idx & 511);
    int rs = (int)(idx >> 9);
    int hw = rs & 1023;
    int bf = rs >> 10;
    int b  = bf >> 3;
    int f  = bf & 7;
    int rt = ((b << 10) + hw) * 8 + f;
    out[idx] = in[(size_t)rt * 512 + c];
}

// ---------------------------------------------------------------------------
// FF activation: y = a * gelu(gate) with f-axis channel shift for c>=683,
// then rms-norm(1365) * ff_gamma
// ---------------------------------------------------------------------------
__global__ void ff_act_rms_k(const float* __restrict__ hdn,
                             const float* __restrict__ gamma,
                             float* __restrict__ yn) {
    int r = blockIdx.x;                       // spatial row (b*8+f)*1024+hw
    int f = (r >> 10) & 7;
    const float* row0 = hdn + (size_t)r * FF2;
    const float* row1 = (f > 0) ? (hdn + (size_t)(r - 1024) * FF2) : (const float*)0;
    __shared__ float ybuf[FFI];
    __shared__ float red[256];
    int t = threadIdx.x;
    float ss = 0.0f;
    for (int c = t; c < FFI; c += 256) {
        float a, g;
        if (c < 683)      { a = row0[c]; g = row0[FFI + c]; }
        else if (row1)    { a = row1[c]; g = row1[FFI + c]; }
        else              { a = 0.0f;    g = 0.0f; }
        float gl = 0.5f * g * (1.0f + erff(g * 0.70710678118654752f));
        float y = a * gl;
        ybuf[c] = y;
        ss += y * y;
    }
    red[t] = ss; __syncthreads();
    for (int st = 128; st > 0; st >>= 1) {
        if (t < st) red[t] += red[t + st];
        __syncthreads();
    }
    float scale = sqrtf((float)FFI) / fmaxf(sqrtf(red[0]), 1e-12f);
    for (int c = t; c < FFI; c += 256)
        yn[(size_t)r * FFI + c] = ybuf[c] * scale * gamma[c];
}

// ---------------------------------------------------------------------------
// Host orchestration
// ---------------------------------------------------------------------------
static float *p_xs = 0, *p_xn, *p_q, *p_kv, *p_o, *p_t, *p_yn, *p_s, *p_tab2, *p_tab1;

static void init_ptrs() {
    if (p_xs) return;
    cudaGetSymbolAddress((void**)&p_xs,   g_xs);
    cudaGetSymbolAddress((void**)&p_xn,   g_xn);
    cudaGetSymbolAddress((void**)&p_q,    g_q);
    cudaGetSymbolAddress((void**)&p_kv,   g_kv);
    cudaGetSymbolAddress((void**)&p_o,    g_o);
    cudaGetSymbolAddress((void**)&p_t,    g_t);
    cudaGetSymbolAddress((void**)&p_yn,   g_yn);
    cudaGetSymbolAddress((void**)&p_s,    g_s);
    cudaGetSymbolAddress((void**)&p_tab2, g_tab2);
    cudaGetSymbolAddress((void**)&p_tab1, g_tab1);
}

extern "C" void kernel_launch(void* const* d_in, const int* in_sizes, int n_in,
                              void* d_out, int out_size) {
    (void)in_sizes; (void)n_in; (void)out_size;
    init_ptrs();

    const float* x        = (const float*)d_in[0];
    const float* sa_gamma = (const float*)d_in[1];
    const float* sa_wq    = (const float*)d_in[2];
    const float* sa_wkv   = (const float*)d_in[3];
    const float* sa_wo    = (const float*)d_in[4];
    const float* ta_gamma = (const float*)d_in[5];
    const float* ta_wq    = (const float*)d_in[6];
    const float* ta_wkv   = (const float*)d_in[7];
    const float* ta_wo    = (const float*)d_in[8];
    const float* sp_w1    = (const float*)d_in[9];
    const float* sp_b1    = (const float*)d_in[10];
    const float* sp_w2    = (const float*)d_in[11];
    const float* sp_b2    = (const float*)d_in[12];
    const float* sp_w3    = (const float*)d_in[13];
    const float* sp_b3    = (const float*)d_in[14];
    const float* tp_w1    = (const float*)d_in[15];
    const float* tp_b1    = (const float*)d_in[16];
    const float* tp_w2    = (const float*)d_in[17];
    const float* tp_b2    = (const float*)d_in[18];
    const float* tp_w3    = (const float*)d_in[19];
    const float* tp_b3    = (const float*)d_in[20];
    const float* ff_win   = (const float*)d_in[21];
    const float* ff_gamma = (const float*)d_in[22];
    const float* ff_wout  = (const float*)d_in[23];
    float* out = (float*)d_out;

    dim3 tb(32, 8);

    // (B,C,F,H,W) -> spatial layout (b,f,hw,c): per b transpose (512 x 8192)
    transpose_k<<<dim3(8192 / 32, 512 / 32, 2), tb>>>(x, p_xs, 512, 8192);

    // CPB bias tables
    cpb2_k<<<3969, 256>>>(sp_w1, sp_b1, sp_w2, sp_b2, sp_w3, sp_b3, p_tab2);
    cpb1_k<<<15,   256>>>(tp_w1, tp_b1, tp_w2, tp_b2, tp_w3, tp_b3, p_tab1);

    // ---- spatial attention ----
    rmsnorm_k<<<TOK, 256>>>(p_xs, sa_gamma, p_xn);
    gemm_k<<<dim3(512 / GBN,  TOK / GBM), 256>>>(p_xn, sa_wq,  0, p_q,  TOK, 512,  512);
    gemm_k<<<dim3(1024 / GBN, TOK / GBM), 256>>>(p_xn, sa_wkv, 0, p_kv, TOK, 1024, 512);
    scores_k<<<dim3(16, 16, 128), 256>>>(p_q, p_kv, p_tab2, p_s);
    softmax_k<<<131072, 256>>>(p_s);
    av_k<<<dim3(1, 16, 128), 256>>>(p_s, p_kv, p_o);
    gemm_k<<<dim3(512 / GBN, TOK / GBM), 256>>>(p_o, sa_wo, p_xs, p_xs, TOK, 512, 512);

    // ---- temporal attention ----
    sp2tmp_k<<<TOK * 512 / 256, 256>>>(p_xs, p_t);
    rmsnorm_k<<<TOK, 256>>>(p_t, ta_gamma, p_xn);
    gemm_k<<<dim3(512 / GBN,  TOK / GBM), 256>>>(p_xn, ta_wq,  0, p_q,  TOK, 512,  512);
    gemm_k<<<dim3(1024 / GBN, TOK / GBM), 256>>>(p_xn, ta_wkv, 0, p_kv, TOK, 1024, 512);
    tattn_k<<<2048, 256>>>(p_q, p_kv, p_tab1, p_o);
    gemm_k<<<dim3(512 / GBN, TOK / GBM), 256>>>(p_o, ta_wo, p_t, p_t, TOK, 512, 512);
    tmp2sp_k<<<TOK * 512 / 256, 256>>>(p_t, p_xs);

    // ---- feed-forward ----
    gemm_k<<<dim3((FF2 + GBN - 1) / GBN, TOK / GBM), 256>>>(p_xs, ff_win, 0, p_s, TOK, FF2, 512);
    ff_act_rms_k<<<TOK, 256>>>(p_s, ff_gamma, p_yn);
    gemm_k<<<dim3(512 / GBN, TOK / GBM), 256>>>(p_yn, ff_wout, p_xs, p_xs, TOK, 512, FFI);

    // spatial layout -> (B,C,F,H,W): per b transpose (8192 x 512)
    transpose_k<<<dim3(512 / 32, 8192 / 32, 2), tb>>>(p_xs, out, 8192, 512);
}